// round 11
// baseline (speedup 1.0000x reference)
#include <cuda_runtime.h>
#include <math.h>

#define N_ATOMS 1500
#define NODE_DIM 128
#define HIDDEN 64
#define SPH_DIM 480
#define OFF0 128
#define MUL1E 64
#define HID1E 32
#define NUM_BASIS 20
#define CUTOFF 5.0f

#define TB 512               /* threads per edge block */
#define BTILE 512            /* b's per block (1 edge/thread): 1500 = 512+512+476 */
#define TA 4

#define NPB 5
#define NB_NODE 300          /* 300*5 = 1500 exactly */
#define NB_TAB 2
#define TAB_N 512
#define TAB_RANGE 8.0f       /* fc underflows to 0 beyond d ~ 8 */

// node n: [coord.xyz, ni.xyz, nj.xyz] as 3x float4
__device__ float4 g_node[N_ATOMS * 3];
// entry i: (0.5*fc(x_i), 0.5*fc(x_{i+1})), x_i = i*TAB_RANGE/TAB_N
__device__ float2 g_fc2[TAB_N + 1];

__device__ __forceinline__ float sigmoidf_(float x) {
    return 1.0f / (1.0f + __expf(-x));
}

__device__ __forceinline__ unsigned smem_u32(const void* p) {
    unsigned a;
    asm("{ .reg .u64 t; cvta.to.shared.u64 t, %1; cvt.u32.u64 %0, t; }"
        : "=r"(a) : "l"(p));
    return a;
}

// ---------------------------------------------------------------------------
// Stage 1: per-node MLPs, 5 nodes per block. Extra blocks build the fc table.
// Thread roles (384 threads):
//   [0,128)   scalar MLPs (2 sets x 64 hidden cols) + warp-shuffle reduce
//   [128,320) spherical MLPs (2 sets x 32 hidden x 3 dims)
// ---------------------------------------------------------------------------
__global__ __launch_bounds__(384, 4) void node_kernel(
    const float* __restrict__ xs_g, const float* __restrict__ xsph,
    const float* __restrict__ coord,
    const float* __restrict__ Wsi1, const float* __restrict__ Wsi2,
    const float* __restrict__ Wsj1, const float* __restrict__ Wsj2,
    const float* __restrict__ Wpi1, const float* __restrict__ Wpi2,
    const float* __restrict__ Wpj1, const float* __restrict__ Wpj2,
    const float* __restrict__ Wrbf)
{
    int tid = threadIdx.x;

    if (blockIdx.x >= NB_NODE) {
        // ---- fc table build (pairs) ----
        const float dO = CUTOFF / (float)(NUM_BASIS - 1);
        const float c2e = (-0.5f / (dO * dO)) * 1.4426950408889634f;
        float w[NUM_BASIS];
        #pragma unroll
        for (int k = 0; k < NUM_BASIS; k++) w[k] = __ldg(&Wrbf[k]);
        for (int i = (blockIdx.x - NB_NODE) * 384 + tid; i <= TAB_N; i += NB_TAB * 384) {
            float2 r;
            float x0 = (float)i * (TAB_RANGE / (float)TAB_N);
            float x1 = (float)(i + 1) * (TAB_RANGE / (float)TAB_N);
            float f0 = 0.f, f1 = 0.f;
            #pragma unroll
            for (int k = 0; k < NUM_BASIS; k++) {
                float t0 = x0 - (float)k * dO;
                float t1 = x1 - (float)k * dO;
                f0 = fmaf(w[k], exp2f((c2e * t0) * t0), f0);
                f1 = fmaf(w[k], exp2f((c2e * t1) * t1), f1);
            }
            r.x = 0.5f * f0; r.y = 0.5f * f1;
            g_fc2[i] = r;
        }
        return;
    }

    __shared__ __align__(16) float xs[NPB * NODE_DIM];   // 2.5 KB
    __shared__ float vv[NPB * 192];
    __shared__ float hh[NPB * 192];
    __shared__ float hg[NPB * 192];
    __shared__ float spart[4][NPB];      // per-warp scalar partial sums
    __shared__ float outp[NPB][2][3];

    int n0 = blockIdx.x * NPB;

    for (int i = tid; i < NPB * NODE_DIM; i += 384) xs[i] = xs_g[n0 * NODE_DIM + i];
    for (int i = tid; i < NPB * 192; i += 384) {
        int n = i / 192, k = i - n * 192;
        vv[i] = xsph[(size_t)(n0 + n) * SPH_DIM + OFF0 + k];
    }
    __syncthreads();

    if (tid < 128) {
        int set = tid >> 6, col = tid & 63;
        const float* W1 = set ? Wsj1 : Wsi1;
        const float* W2 = set ? Wsj2 : Wsi2;
        float acc[NPB];
        #pragma unroll
        for (int n = 0; n < NPB; n++) acc[n] = 0.f;
        const float4* xs4 = (const float4*)xs;
        #pragma unroll 4
        for (int k = 0; k < NODE_DIM; k += 4) {
            float w0 = __ldg(&W1[(k + 0) * HIDDEN + col]);
            float w1 = __ldg(&W1[(k + 1) * HIDDEN + col]);
            float w2 = __ldg(&W1[(k + 2) * HIDDEN + col]);
            float w3 = __ldg(&W1[(k + 3) * HIDDEN + col]);
            #pragma unroll
            for (int n = 0; n < NPB; n++) {
                float4 x = xs4[n * (NODE_DIM / 4) + (k >> 2)];
                acc[n] = fmaf(x.x, w0, acc[n]);
                acc[n] = fmaf(x.y, w1, acc[n]);
                acc[n] = fmaf(x.z, w2, acc[n]);
                acc[n] = fmaf(x.w, w3, acc[n]);
            }
        }
        float w2c = __ldg(&W2[col]);
        // warp shuffle reduce over the 32 cols in this warp, for each node
        #pragma unroll
        for (int n = 0; n < NPB; n++) {
            float a = acc[n];
            float v = a * sigmoidf_(a) * w2c;    // silu * W2
            v += __shfl_xor_sync(0xffffffffu, v, 16);
            v += __shfl_xor_sync(0xffffffffu, v, 8);
            v += __shfl_xor_sync(0xffffffffu, v, 4);
            v += __shfl_xor_sync(0xffffffffu, v, 2);
            v += __shfl_xor_sync(0xffffffffu, v, 1);
            if ((tid & 31) == 0) spart[tid >> 5][n] = v;
        }
    } else if (tid < 320) {
        int t = tid - 128;
        int set = t / 96;
        int r = t - set * 96;
        int hc = r / 3, dd = r - hc * 3;
        const float* W1 = set ? Wpj1 : Wpi1;
        float acc[NPB];
        #pragma unroll
        for (int n = 0; n < NPB; n++) acc[n] = 0.f;
        #pragma unroll 4
        for (int m = 0; m < MUL1E; m++) {
            float w = __ldg(&W1[m * HID1E + hc]);
            #pragma unroll
            for (int n = 0; n < NPB; n++)
                acc[n] = fmaf(vv[n * 192 + m * 3 + dd], w, acc[n]);
        }
        #pragma unroll
        for (int n = 0; n < NPB; n++)
            hh[n * 192 + set * 96 + hc * 3 + dd] = acc[n] * 0.125f;   // 1/sqrt(64)
    }
    __syncthreads();

    if (tid >= 128 && tid < 320) {
        int t = tid - 128;
        int set = t / 96;
        int r = t - set * 96;
        int hc = r / 3, dd = r - hc * 3;
        const float* W2 = set ? Wpj2 : Wpi2;
        float w2c = __ldg(&W2[hc]);
        #pragma unroll
        for (int n = 0; n < NPB; n++) {
            int base = n * 192 + set * 96 + hc * 3;
            float h0 = hh[base + 0], h1 = hh[base + 1], h2 = hh[base + 2];
            float nrm = sqrtf(h0 * h0 + h1 * h1 + h2 * h2);
            float gate = sigmoidf_(nrm);
            hg[base + dd] = hh[base + dd] * gate * w2c;
        }
    }
    __syncthreads();

    if (tid < NPB * 6) {                       // (n, set, dd) spherical reduce, 4-way ILP
        int n = tid / 6;
        int r = tid - n * 6;
        int set = r / 3, dd = r - set * 3;
        int base = n * 192 + set * 96 + dd;
        float s0 = 0.f, s1 = 0.f, s2 = 0.f, s3 = 0.f;
        #pragma unroll
        for (int hc = 0; hc < HID1E; hc += 4) {
            s0 += hg[base + (hc + 0) * 3];
            s1 += hg[base + (hc + 1) * 3];
            s2 += hg[base + (hc + 2) * 3];
            s3 += hg[base + (hc + 3) * 3];
        }
        outp[n][set][dd] = ((s0 + s1) + (s2 + s3)) * 0.17677669529663687f;   // 1/sqrt(32)
    }
    __syncthreads();

    if (tid < NPB) {
        int n = n0 + tid;
        float fi = 1.f + spart[0][tid] + spart[1][tid];
        float fj = 1.f + spart[2][tid] + spart[3][tid];
        // e3nn 1e (y,z,x) -> (x,y,z): out[:, [2,0,1]]
        g_node[n * 3 + 0] = make_float4(coord[n * 3 + 0], coord[n * 3 + 1], coord[n * 3 + 2], 0.f);
        g_node[n * 3 + 1] = make_float4(outp[tid][0][2] * fi, outp[tid][0][0] * fi, outp[tid][0][1] * fi, 0.f);
        g_node[n * 3 + 2] = make_float4(outp[tid][1][2] * fj, outp[tid][1][0] * fj, outp[tid][1][1] * fj, 0.f);
    }
}

// ---------------------------------------------------------------------------
// Stage 2: edges. 512 threads x 1 edge each = 512-b tile, x TA=4 a-values.
// out[a*N+b][r][c] = 0.5 * fc(d_ab) * (ni_a[r]*nj_b[c] + nj_a[r]*ni_b[c])
// Per-thread stage stride = 9 floats (gcd(9,32)=1) -> conflict-free STS.
// Double-buffered stage + TMA bulk S2G; wait only for the ai-2 copy.
// ---------------------------------------------------------------------------
__global__ __launch_bounds__(TB, 3) void edge_kernel(float* __restrict__ out)
{
    __shared__ __align__(16) float stage[2][BTILE * 9];  // 36 KB
    __shared__ float2 tab2[TAB_N + 1];                   // ~4 KB

    int tid = threadIdx.x;
    for (int i = tid; i <= TAB_N; i += TB)
        tab2[i] = __ldg(&g_fc2[i]);

    int b0 = blockIdx.x * BTILE;
    int nb = min(BTILE, N_ATOMS - b0);       // 512 or 476
    bool valid = tid < nb;

    const float4* gn = (const float4*)g_node;
    float4 cb = {}, nib = {}, njb = {};
    if (valid) {
        int b = b0 + tid;
        cb  = __ldg(&gn[b * 3 + 0]);
        nib = __ldg(&gn[b * 3 + 1]);
        njb = __ldg(&gn[b * 3 + 2]);
    }
    const float scale = (float)TAB_N / TAB_RANGE;
    __syncthreads();

    #pragma unroll
    for (int ai = 0; ai < TA; ai++) {
        int a = blockIdx.y * TA + ai;
        float4 ca  = __ldg(&gn[a * 3 + 0]);
        float4 nia = __ldg(&gn[a * 3 + 1]);
        float4 nja = __ldg(&gn[a * 3 + 2]);

        // the copy issued from this buffer two iterations ago must be done
        if (ai >= 2 && tid == 0)
            asm volatile("cp.async.bulk.wait_group %0;" :: "n"(1) : "memory");
        __syncthreads();

        if (valid) {
            float dx = ca.x - cb.x, dy = ca.y - cb.y, dz = ca.z - cb.z;
            float d2 = fmaf(dx, dx, fmaf(dy, dy, dz * dz));
            float d;
            asm("sqrt.approx.f32 %0, %1;" : "=f"(d) : "f"(d2));  // sqrt(0)=0 ok

            float u = fminf(d * scale, (float)TAB_N - 0.001f);
            int i = __float2int_rd(u);
            float frac = u - (float)i;
            float2 t = tab2[i];
            float f = fmaf(frac, t.y - t.x, t.x);      // 0.5*fc(d)

            float fjx = f * njb.x, fjy = f * njb.y, fjz = f * njb.z;
            float fax = f * nja.x, fay = f * nja.y, faz = f * nja.z;

            float* st = &stage[ai & 1][tid * 9];
            st[0] = fmaf(nia.x, fjx, fax * nib.x);
            st[1] = fmaf(nia.x, fjy, fax * nib.y);
            st[2] = fmaf(nia.x, fjz, fax * nib.z);
            st[3] = fmaf(nia.y, fjx, fay * nib.x);
            st[4] = fmaf(nia.y, fjy, fay * nib.y);
            st[5] = fmaf(nia.y, fjz, fay * nib.z);
            st[6] = fmaf(nia.z, fjx, faz * nib.x);
            st[7] = fmaf(nia.z, fjy, faz * nib.y);
            st[8] = fmaf(nia.z, fjz, faz * nib.z);
        }
        __syncthreads();

        if (tid == 0) {
            asm volatile("fence.proxy.async.shared::cta;" ::: "memory");
            float* gdst = out + ((size_t)a * N_ATOMS + b0) * 9;   // 16B aligned
            unsigned bytes = (unsigned)(nb * 9 * 4);              // 16B multiple
            unsigned sa = smem_u32(&stage[ai & 1][0]);
            asm volatile("cp.async.bulk.global.shared::cta.bulk_group [%0], [%1], %2;"
                         :: "l"(gdst), "r"(sa), "r"(bytes) : "memory");
            asm volatile("cp.async.bulk.commit_group;" ::: "memory");
        }
    }

    // keep CTA (and its smem) alive until all outstanding copies drain
    if (tid == 0)
        asm volatile("cp.async.bulk.wait_group %0;" :: "n"(0) : "memory");
}

extern "C" void kernel_launch(void* const* d_in, const int* in_sizes, int n_in,
                              void* d_out, int out_size)
{
    const float* xs    = (const float*)d_in[0];
    const float* xsph  = (const float*)d_in[1];
    const float* coord = (const float*)d_in[2];
    // d_in[3] = fc_edge_index (full graph, i-major; structure known, unused)
    const float* Wsi1 = (const float*)d_in[4];
    const float* Wsi2 = (const float*)d_in[5];
    const float* Wsj1 = (const float*)d_in[6];
    const float* Wsj2 = (const float*)d_in[7];
    const float* Wpi1 = (const float*)d_in[8];
    const float* Wpi2 = (const float*)d_in[9];
    const float* Wpj1 = (const float*)d_in[10];
    const float* Wpj2 = (const float*)d_in[11];
    const float* Wrbf = (const float*)d_in[12];

    node_kernel<<<NB_NODE + NB_TAB, 384>>>(xs, xsph, coord,
                                           Wsi1, Wsi2, Wsj1, Wsj2,
                                           Wpi1, Wpi2, Wpj1, Wpj2, Wrbf);

    dim3 grid((N_ATOMS + BTILE - 1) / BTILE, N_ATOMS / TA);
    edge_kernel<<<grid, TB>>>((float*)d_out);
}

// round 12
// speedup vs baseline: 1.0567x; 1.0567x over previous
#include <cuda_runtime.h>
#include <math.h>

#define N_ATOMS 1500
#define NODE_DIM 128
#define HIDDEN 64
#define SPH_DIM 480
#define OFF0 128
#define MUL1E 64
#define HID1E 32
#define NUM_BASIS 20
#define CUTOFF 5.0f

#define TB 256               /* threads per edge block, 8 warps */
#define BTILE 256            /* b's per block (1 edge/thread-lane) */
#define TA 4                 /* a's per block */

#define NPB 5
#define NB_NODE 300          /* 300*5 = 1500 exactly */
#define NB_TAB 2
#define TAB_N 1024
#define TAB_RANGE 8.0f       /* fc underflows to 0 beyond d ~ 8 */

// node n: [coord.xyz, ni.xyz, nj.xyz] as 3x float4
__device__ float4 g_node[N_ATOMS * 3];
// entry i: (0.5*fc(x_i), 0.5*fc(x_{i+1})), x_i = i*TAB_RANGE/TAB_N
__device__ float2 g_fc2[TAB_N + 1];

__device__ __forceinline__ float sigmoidf_(float x) {
    return 1.0f / (1.0f + __expf(-x));
}

// ---------------------------------------------------------------------------
// Stage 1: per-node MLPs, 5 nodes per block. Extra blocks build the fc table.
// ---------------------------------------------------------------------------
__global__ __launch_bounds__(384, 4) void node_kernel(
    const float* __restrict__ xs_g, const float* __restrict__ xsph,
    const float* __restrict__ coord,
    const float* __restrict__ Wsi1, const float* __restrict__ Wsi2,
    const float* __restrict__ Wsj1, const float* __restrict__ Wsj2,
    const float* __restrict__ Wpi1, const float* __restrict__ Wpi2,
    const float* __restrict__ Wpj1, const float* __restrict__ Wpj2,
    const float* __restrict__ Wrbf)
{
    int tid = threadIdx.x;

    if (blockIdx.x >= NB_NODE) {
        // ---- fc table build (pairs) ----
        const float dO = CUTOFF / (float)(NUM_BASIS - 1);
        const float c2e = (-0.5f / (dO * dO)) * 1.4426950408889634f;
        float w[NUM_BASIS];
        #pragma unroll
        for (int k = 0; k < NUM_BASIS; k++) w[k] = __ldg(&Wrbf[k]);
        for (int i = (blockIdx.x - NB_NODE) * 384 + tid; i <= TAB_N; i += NB_TAB * 384) {
            float2 r;
            float x0 = (float)i * (TAB_RANGE / (float)TAB_N);
            float x1 = (float)(i + 1) * (TAB_RANGE / (float)TAB_N);
            float f0 = 0.f, f1 = 0.f;
            #pragma unroll
            for (int k = 0; k < NUM_BASIS; k++) {
                float t0 = x0 - (float)k * dO;
                float t1 = x1 - (float)k * dO;
                f0 = fmaf(w[k], exp2f((c2e * t0) * t0), f0);
                f1 = fmaf(w[k], exp2f((c2e * t1) * t1), f1);
            }
            r.x = 0.5f * f0; r.y = 0.5f * f1;
            g_fc2[i] = r;
        }
        return;
    }

    __shared__ __align__(16) float xs[NPB * NODE_DIM];   // 2.5 KB
    __shared__ float vv[NPB * 192];
    __shared__ float hh[NPB * 192];
    __shared__ float hg[NPB * 192];
    __shared__ float spart[4][NPB];      // per-warp scalar partial sums
    __shared__ float outp[NPB][2][3];

    int n0 = blockIdx.x * NPB;

    for (int i = tid; i < NPB * NODE_DIM; i += 384) xs[i] = xs_g[n0 * NODE_DIM + i];
    for (int i = tid; i < NPB * 192; i += 384) {
        int n = i / 192, k = i - n * 192;
        vv[i] = xsph[(size_t)(n0 + n) * SPH_DIM + OFF0 + k];
    }
    __syncthreads();

    if (tid < 128) {
        int set = tid >> 6, col = tid & 63;
        const float* W1 = set ? Wsj1 : Wsi1;
        const float* W2 = set ? Wsj2 : Wsi2;
        float acc[NPB];
        #pragma unroll
        for (int n = 0; n < NPB; n++) acc[n] = 0.f;
        const float4* xs4 = (const float4*)xs;
        #pragma unroll 4
        for (int k = 0; k < NODE_DIM; k += 4) {
            float w0 = __ldg(&W1[(k + 0) * HIDDEN + col]);
            float w1 = __ldg(&W1[(k + 1) * HIDDEN + col]);
            float w2 = __ldg(&W1[(k + 2) * HIDDEN + col]);
            float w3 = __ldg(&W1[(k + 3) * HIDDEN + col]);
            #pragma unroll
            for (int n = 0; n < NPB; n++) {
                float4 x = xs4[n * (NODE_DIM / 4) + (k >> 2)];
                acc[n] = fmaf(x.x, w0, acc[n]);
                acc[n] = fmaf(x.y, w1, acc[n]);
                acc[n] = fmaf(x.z, w2, acc[n]);
                acc[n] = fmaf(x.w, w3, acc[n]);
            }
        }
        float w2c = __ldg(&W2[col]);
        // warp shuffle reduce over the 32 cols in this warp, for each node
        #pragma unroll
        for (int n = 0; n < NPB; n++) {
            float a = acc[n];
            float v = a * sigmoidf_(a) * w2c;    // silu * W2
            v += __shfl_xor_sync(0xffffffffu, v, 16);
            v += __shfl_xor_sync(0xffffffffu, v, 8);
            v += __shfl_xor_sync(0xffffffffu, v, 4);
            v += __shfl_xor_sync(0xffffffffu, v, 2);
            v += __shfl_xor_sync(0xffffffffu, v, 1);
            if ((tid & 31) == 0) spart[tid >> 5][n] = v;
        }
    } else if (tid < 320) {
        int t = tid - 128;
        int set = t / 96;
        int r = t - set * 96;
        int hc = r / 3, dd = r - hc * 3;
        const float* W1 = set ? Wpj1 : Wpi1;
        float acc[NPB];
        #pragma unroll
        for (int n = 0; n < NPB; n++) acc[n] = 0.f;
        #pragma unroll 4
        for (int m = 0; m < MUL1E; m++) {
            float w = __ldg(&W1[m * HID1E + hc]);
            #pragma unroll
            for (int n = 0; n < NPB; n++)
                acc[n] = fmaf(vv[n * 192 + m * 3 + dd], w, acc[n]);
        }
        #pragma unroll
        for (int n = 0; n < NPB; n++)
            hh[n * 192 + set * 96 + hc * 3 + dd] = acc[n] * 0.125f;   // 1/sqrt(64)
    }
    __syncthreads();

    if (tid >= 128 && tid < 320) {
        int t = tid - 128;
        int set = t / 96;
        int r = t - set * 96;
        int hc = r / 3, dd = r - hc * 3;
        const float* W2 = set ? Wpj2 : Wpi2;
        float w2c = __ldg(&W2[hc]);
        #pragma unroll
        for (int n = 0; n < NPB; n++) {
            int base = n * 192 + set * 96 + hc * 3;
            float h0 = hh[base + 0], h1 = hh[base + 1], h2 = hh[base + 2];
            float nrm = sqrtf(h0 * h0 + h1 * h1 + h2 * h2);
            float gate = sigmoidf_(nrm);
            hg[base + dd] = hh[base + dd] * gate * w2c;
        }
    }
    __syncthreads();

    if (tid < NPB * 6) {                       // (n, set, dd) spherical reduce, 4-way ILP
        int n = tid / 6;
        int r = tid - n * 6;
        int set = r / 3, dd = r - set * 3;
        int base = n * 192 + set * 96 + dd;
        float s0 = 0.f, s1 = 0.f, s2 = 0.f, s3 = 0.f;
        #pragma unroll
        for (int hc = 0; hc < HID1E; hc += 4) {
            s0 += hg[base + (hc + 0) * 3];
            s1 += hg[base + (hc + 1) * 3];
            s2 += hg[base + (hc + 2) * 3];
            s3 += hg[base + (hc + 3) * 3];
        }
        outp[n][set][dd] = ((s0 + s1) + (s2 + s3)) * 0.17677669529663687f;   // 1/sqrt(32)
    }
    __syncthreads();

    if (tid < NPB) {
        int n = n0 + tid;
        float fi = 1.f + spart[0][tid] + spart[1][tid];
        float fj = 1.f + spart[2][tid] + spart[3][tid];
        // e3nn 1e (y,z,x) -> (x,y,z): out[:, [2,0,1]]
        g_node[n * 3 + 0] = make_float4(coord[n * 3 + 0], coord[n * 3 + 1], coord[n * 3 + 2], 0.f);
        g_node[n * 3 + 1] = make_float4(outp[tid][0][2] * fi, outp[tid][0][0] * fi, outp[tid][0][1] * fi, 0.f);
        g_node[n * 3 + 2] = make_float4(outp[tid][1][2] * fj, outp[tid][1][0] * fj, outp[tid][1][1] * fj, 0.f);
    }
}

// ---------------------------------------------------------------------------
// Stage 2: edges, warp-autonomous. Each warp owns 32 consecutive b's; per a it
// computes the 9 components into a private smem slice (stride-9 STS,
// conflict-free), __syncwarp, then 9 coalesced LDS+STG rounds. No
// __syncthreads in the mainloop, no TMA, no cross-warp coupling.
// out[a*N+b][r][c] = 0.5 * fc(d_ab) * (ni_a[r]*nj_b[c] + nj_a[r]*ni_b[c])
// ---------------------------------------------------------------------------
__global__ __launch_bounds__(TB, 5) void edge_kernel(float* __restrict__ out)
{
    __shared__ float stage[TB * 9];          // 9 KB: 8 warp slices of 288 floats
    __shared__ float2 tab2[TAB_N + 1];       // 8.2 KB

    int tid = threadIdx.x;
    int lane = tid & 31;
    int warp = tid >> 5;

    for (int i = tid; i <= TAB_N; i += TB)
        tab2[i] = __ldg(&g_fc2[i]);

    int bw0 = blockIdx.x * BTILE + warp * 32;      // this warp's first b
    int b = bw0 + lane;
    int bc = min(b, N_ATOMS - 1);                  // clamped for safe loads
    // number of valid words in this warp's 288-float output region
    int wlimit = max(0, min(32, N_ATOMS - bw0)) * 9;

    const float4* gn = (const float4*)g_node;
    float4 cb  = __ldg(&gn[bc * 3 + 0]);
    float4 nib = __ldg(&gn[bc * 3 + 1]);
    float4 njb = __ldg(&gn[bc * 3 + 2]);

    const float scale = (float)TAB_N / TAB_RANGE;
    float* st = &stage[warp * 288 + lane * 9];
    const float* slice = &stage[warp * 288];
    __syncthreads();                               // table visible to all warps

    #pragma unroll
    for (int ai = 0; ai < TA; ai++) {
        int a = blockIdx.y * TA + ai;
        float4 ca  = __ldg(&gn[a * 3 + 0]);
        float4 nia = __ldg(&gn[a * 3 + 1]);
        float4 nja = __ldg(&gn[a * 3 + 2]);

        float dx = ca.x - cb.x, dy = ca.y - cb.y, dz = ca.z - cb.z;
        float d2 = fmaf(dx, dx, fmaf(dy, dy, dz * dz));
        float d;
        asm("sqrt.approx.f32 %0, %1;" : "=f"(d) : "f"(d2));   // sqrt(0)=0 ok

        float u = fminf(d * scale, (float)TAB_N - 0.001f);
        int i = __float2int_rd(u);
        float frac = u - (float)i;
        float2 t = tab2[i];
        float f = fmaf(frac, t.y - t.x, t.x);      // 0.5*fc(d)

        float fjx = f * njb.x, fjy = f * njb.y, fjz = f * njb.z;
        float fax = f * nja.x, fay = f * nja.y, faz = f * nja.z;

        __syncwarp();                              // slice free from prev iter
        st[0] = fmaf(nia.x, fjx, fax * nib.x);
        st[1] = fmaf(nia.x, fjy, fax * nib.y);
        st[2] = fmaf(nia.x, fjz, fax * nib.z);
        st[3] = fmaf(nia.y, fjx, fay * nib.x);
        st[4] = fmaf(nia.y, fjy, fay * nib.y);
        st[5] = fmaf(nia.y, fjz, fay * nib.z);
        st[6] = fmaf(nia.z, fjx, faz * nib.x);
        st[7] = fmaf(nia.z, fjy, faz * nib.y);
        st[8] = fmaf(nia.z, fjz, faz * nib.z);
        __syncwarp();

        // coalesced drain: 9 rounds of 32 consecutive words
        float* gdst = out + ((size_t)a * N_ATOMS + bw0) * 9;
        #pragma unroll
        for (int s = 0; s < 9; s++) {
            int p = s * 32 + lane;
            if (p < wlimit) gdst[p] = slice[p];
        }
    }
}

extern "C" void kernel_launch(void* const* d_in, const int* in_sizes, int n_in,
                              void* d_out, int out_size)
{
    const float* xs    = (const float*)d_in[0];
    const float* xsph  = (const float*)d_in[1];
    const float* coord = (const float*)d_in[2];
    // d_in[3] = fc_edge_index (full graph, i-major; structure known, unused)
    const float* Wsi1 = (const float*)d_in[4];
    const float* Wsi2 = (const float*)d_in[5];
    const float* Wsj1 = (const float*)d_in[6];
    const float* Wsj2 = (const float*)d_in[7];
    const float* Wpi1 = (const float*)d_in[8];
    const float* Wpi2 = (const float*)d_in[9];
    const float* Wpj1 = (const float*)d_in[10];
    const float* Wpj2 = (const float*)d_in[11];
    const float* Wrbf = (const float*)d_in[12];

    node_kernel<<<NB_NODE + NB_TAB, 384>>>(xs, xsph, coord,
                                           Wsi1, Wsi2, Wsj1, Wsj2,
                                           Wpi1, Wpi2, Wpj1, Wpj2, Wrbf);

    dim3 grid((N_ATOMS + BTILE - 1) / BTILE, N_ATOMS / TA);   // (6, 375)
    edge_kernel<<<grid, TB>>>((float*)d_out);
}

// round 15
// speedup vs baseline: 1.1299x; 1.0693x over previous
#include <cuda_runtime.h>
#include <math.h>

#define N_ATOMS 1500
#define NODE_DIM 128
#define HIDDEN 64
#define SPH_DIM 480
#define OFF0 128
#define MUL1E 64
#define HID1E 32
#define NUM_BASIS 20
#define CUTOFF 5.0f

#define TB 256               /* threads per edge block, 8 warps */
#define BTILE 256            /* b's per block (1 edge/thread-lane) */
#define TA 4                 /* a's per block */

#define NPB 5
#define NB_NODE 300          /* 300*5 = 1500 exactly */
#define NB_TAB 2
#define TAB_N 1024
#define TAB_RANGE 8.0f       /* fc underflows to 0 beyond d ~ 8 */

// node n: [coord.xyz, ni.xyz, nj.xyz] as 3x float4
__device__ float4 g_node[N_ATOMS * 3];
// entry i: (0.5*fc(x_i), 0.5*fc(x_{i+1})), x_i = i*TAB_RANGE/TAB_N
__device__ float2 g_fc2[TAB_N + 1];

__device__ __forceinline__ float sigmoidf_(float x) {
    return 1.0f / (1.0f + __expf(-x));
}

__device__ __forceinline__ unsigned smem_u32(const void* p) {
    unsigned a;
    asm("{ .reg .u64 t; cvta.to.shared.u64 t, %1; cvt.u32.u64 %0, t; }"
        : "=r"(a) : "l"(p));
    return a;
}

// ---------------------------------------------------------------------------
// Stage 1: per-node MLPs, 5 nodes per block. Extra blocks build the fc table.
// ---------------------------------------------------------------------------
__global__ __launch_bounds__(384, 4) void node_kernel(
    const float* __restrict__ xs_g, const float* __restrict__ xsph,
    const float* __restrict__ coord,
    const float* __restrict__ Wsi1, const float* __restrict__ Wsi2,
    const float* __restrict__ Wsj1, const float* __restrict__ Wsj2,
    const float* __restrict__ Wpi1, const float* __restrict__ Wpi2,
    const float* __restrict__ Wpj1, const float* __restrict__ Wpj2,
    const float* __restrict__ Wrbf)
{
    int tid = threadIdx.x;

    if (blockIdx.x >= NB_NODE) {
        // ---- fc table build (pairs) ----
        const float dO = CUTOFF / (float)(NUM_BASIS - 1);
        const float c2e = (-0.5f / (dO * dO)) * 1.4426950408889634f;
        float w[NUM_BASIS];
        #pragma unroll
        for (int k = 0; k < NUM_BASIS; k++) w[k] = __ldg(&Wrbf[k]);
        for (int i = (blockIdx.x - NB_NODE) * 384 + tid; i <= TAB_N; i += NB_TAB * 384) {
            float2 r;
            float x0 = (float)i * (TAB_RANGE / (float)TAB_N);
            float x1 = (float)(i + 1) * (TAB_RANGE / (float)TAB_N);
            float f0 = 0.f, f1 = 0.f;
            #pragma unroll
            for (int k = 0; k < NUM_BASIS; k++) {
                float t0 = x0 - (float)k * dO;
                float t1 = x1 - (float)k * dO;
                f0 = fmaf(w[k], exp2f((c2e * t0) * t0), f0);
                f1 = fmaf(w[k], exp2f((c2e * t1) * t1), f1);
            }
            r.x = 0.5f * f0; r.y = 0.5f * f1;
            g_fc2[i] = r;
        }
        return;
    }

    __shared__ __align__(16) float xs[NPB * NODE_DIM];   // 2.5 KB
    __shared__ float vv[NPB * 192];
    __shared__ float hh[NPB * 192];
    __shared__ float hg[NPB * 192];
    __shared__ float spart[4][NPB];      // per-warp scalar partial sums
    __shared__ float outp[NPB][2][3];

    int n0 = blockIdx.x * NPB;

    for (int i = tid; i < NPB * NODE_DIM; i += 384) xs[i] = xs_g[n0 * NODE_DIM + i];
    for (int i = tid; i < NPB * 192; i += 384) {
        int n = i / 192, k = i - n * 192;
        vv[i] = xsph[(size_t)(n0 + n) * SPH_DIM + OFF0 + k];
    }
    __syncthreads();

    if (tid < 128) {
        int set = tid >> 6, col = tid & 63;
        const float* W1 = set ? Wsj1 : Wsi1;
        const float* W2 = set ? Wsj2 : Wsi2;
        float acc[NPB];
        #pragma unroll
        for (int n = 0; n < NPB; n++) acc[n] = 0.f;
        const float4* xs4 = (const float4*)xs;
        #pragma unroll 4
        for (int k = 0; k < NODE_DIM; k += 4) {
            float w0 = __ldg(&W1[(k + 0) * HIDDEN + col]);
            float w1 = __ldg(&W1[(k + 1) * HIDDEN + col]);
            float w2 = __ldg(&W1[(k + 2) * HIDDEN + col]);
            float w3 = __ldg(&W1[(k + 3) * HIDDEN + col]);
            #pragma unroll
            for (int n = 0; n < NPB; n++) {
                float4 x = xs4[n * (NODE_DIM / 4) + (k >> 2)];
                acc[n] = fmaf(x.x, w0, acc[n]);
                acc[n] = fmaf(x.y, w1, acc[n]);
                acc[n] = fmaf(x.z, w2, acc[n]);
                acc[n] = fmaf(x.w, w3, acc[n]);
            }
        }
        float w2c = __ldg(&W2[col]);
        // warp shuffle reduce over the 32 cols in this warp, for each node
        #pragma unroll
        for (int n = 0; n < NPB; n++) {
            float a = acc[n];
            float v = a * sigmoidf_(a) * w2c;    // silu * W2
            v += __shfl_xor_sync(0xffffffffu, v, 16);
            v += __shfl_xor_sync(0xffffffffu, v, 8);
            v += __shfl_xor_sync(0xffffffffu, v, 4);
            v += __shfl_xor_sync(0xffffffffu, v, 2);
            v += __shfl_xor_sync(0xffffffffu, v, 1);
            if ((tid & 31) == 0) spart[tid >> 5][n] = v;
        }
    } else if (tid < 320) {
        int t = tid - 128;
        int set = t / 96;
        int r = t - set * 96;
        int hc = r / 3, dd = r - hc * 3;
        const float* W1 = set ? Wpj1 : Wpi1;
        float acc[NPB];
        #pragma unroll
        for (int n = 0; n < NPB; n++) acc[n] = 0.f;
        #pragma unroll 4
        for (int m = 0; m < MUL1E; m++) {
            float w = __ldg(&W1[m * HID1E + hc]);
            #pragma unroll
            for (int n = 0; n < NPB; n++)
                acc[n] = fmaf(vv[n * 192 + m * 3 + dd], w, acc[n]);
        }
        #pragma unroll
        for (int n = 0; n < NPB; n++)
            hh[n * 192 + set * 96 + hc * 3 + dd] = acc[n] * 0.125f;   // 1/sqrt(64)
    }
    __syncthreads();

    if (tid >= 128 && tid < 320) {
        int t = tid - 128;
        int set = t / 96;
        int r = t - set * 96;
        int hc = r / 3, dd = r - hc * 3;
        const float* W2 = set ? Wpj2 : Wpi2;
        float w2c = __ldg(&W2[hc]);
        #pragma unroll
        for (int n = 0; n < NPB; n++) {
            int base = n * 192 + set * 96 + hc * 3;
            float h0 = hh[base + 0], h1 = hh[base + 1], h2 = hh[base + 2];
            float nrm = sqrtf(h0 * h0 + h1 * h1 + h2 * h2);
            float gate = sigmoidf_(nrm);
            hg[base + dd] = hh[base + dd] * gate * w2c;
        }
    }
    __syncthreads();

    if (tid < NPB * 6) {                       // (n, set, dd) spherical reduce, 4-way ILP
        int n = tid / 6;
        int r = tid - n * 6;
        int set = r / 3, dd = r - set * 3;
        int base = n * 192 + set * 96 + dd;
        float s0 = 0.f, s1 = 0.f, s2 = 0.f, s3 = 0.f;
        #pragma unroll
        for (int hc = 0; hc < HID1E; hc += 4) {
            s0 += hg[base + (hc + 0) * 3];
            s1 += hg[base + (hc + 1) * 3];
            s2 += hg[base + (hc + 2) * 3];
            s3 += hg[base + (hc + 3) * 3];
        }
        outp[n][set][dd] = ((s0 + s1) + (s2 + s3)) * 0.17677669529663687f;   // 1/sqrt(32)
    }
    __syncthreads();

    if (tid < NPB) {
        int n = n0 + tid;
        float fi = 1.f + spart[0][tid] + spart[1][tid];
        float fj = 1.f + spart[2][tid] + spart[3][tid];
        // e3nn 1e (y,z,x) -> (x,y,z): out[:, [2,0,1]]
        g_node[n * 3 + 0] = make_float4(coord[n * 3 + 0], coord[n * 3 + 1], coord[n * 3 + 2], 0.f);
        g_node[n * 3 + 1] = make_float4(outp[tid][0][2] * fi, outp[tid][0][0] * fi, outp[tid][0][1] * fi, 0.f);
        g_node[n * 3 + 2] = make_float4(outp[tid][1][2] * fj, outp[tid][1][0] * fj, outp[tid][1][1] * fj, 0.f);
    }
}

// ---------------------------------------------------------------------------
// Stage 2: edges, warp-autonomous with per-warp TMA drain.
// Each warp owns 32 consecutive b's and a private double-buffered smem slice
// (2 x 1152 B). Per a: compute 9 comps (stride-9 STS, conflict-free),
// __syncwarp, elected lane issues cp.async.bulk S2G from the slice.
// bulk_group state is per-thread, so warps never couple; no block barriers
// in the mainloop.
// out[a*N+b][r][c] = 0.5 * fc(d_ab) * (ni_a[r]*nj_b[c] + nj_a[r]*ni_b[c])
// ---------------------------------------------------------------------------
__global__ __launch_bounds__(TB, 5) void edge_kernel(float* __restrict__ out)
{
    __shared__ __align__(16) float stage[8][2][288];   // 18 KB
    __shared__ float2 tab2[TAB_N + 1];                 // 8.2 KB

    int tid = threadIdx.x;
    int lane = tid & 31;
    int warp = tid >> 5;

    for (int i = tid; i <= TAB_N; i += TB)
        tab2[i] = __ldg(&g_fc2[i]);
    __syncthreads();                               // table visible to all warps

    int bw0 = blockIdx.x * BTILE + warp * 32;      // this warp's first b
    int nwarp = min(32, N_ATOMS - bw0);            // 32, 28, or <=0 (idle warp)
    bool active = nwarp > 0;

    int bc = min(bw0 + lane, N_ATOMS - 1);         // clamped for safe loads
    const float4* gn = (const float4*)g_node;
    float4 cb  = __ldg(&gn[bc * 3 + 0]);
    float4 nib = __ldg(&gn[bc * 3 + 1]);
    float4 njb = __ldg(&gn[bc * 3 + 2]);

    const float scale = (float)TAB_N / TAB_RANGE;
    const unsigned bytes = (unsigned)(max(nwarp, 0) * 9 * 4);   // 1152/1008, 16B mult

    #pragma unroll
    for (int ai = 0; ai < TA; ai++) {
        int a = blockIdx.y * TA + ai;
        float4 ca  = __ldg(&gn[a * 3 + 0]);
        float4 nia = __ldg(&gn[a * 3 + 1]);
        float4 nja = __ldg(&gn[a * 3 + 2]);

        float dx = ca.x - cb.x, dy = ca.y - cb.y, dz = ca.z - cb.z;
        float d2 = fmaf(dx, dx, fmaf(dy, dy, dz * dz));
        float d;
        asm("sqrt.approx.f32 %0, %1;" : "=f"(d) : "f"(d2));   // sqrt(0)=0 ok

        float u = fminf(d * scale, (float)TAB_N - 0.001f);
        int i = __float2int_rd(u);
        float frac = u - (float)i;
        float2 t = tab2[i];
        float f = fmaf(frac, t.y - t.x, t.x);      // 0.5*fc(d)

        float fjx = f * njb.x, fjy = f * njb.y, fjz = f * njb.z;
        float fax = f * nja.x, fay = f * nja.y, faz = f * nja.z;

        // buffer reuse: the copy issued from this buffer 2 iters ago must be done
        if (ai >= 2) {
            if (lane == 0)
                asm volatile("cp.async.bulk.wait_group %0;" :: "n"(1) : "memory");
            __syncwarp();
        }

        float* st = &stage[warp][ai & 1][lane * 9];
        st[0] = fmaf(nia.x, fjx, fax * nib.x);
        st[1] = fmaf(nia.x, fjy, fax * nib.y);
        st[2] = fmaf(nia.x, fjz, fax * nib.z);
        st[3] = fmaf(nia.y, fjx, fay * nib.x);
        st[4] = fmaf(nia.y, fjy, fay * nib.y);
        st[5] = fmaf(nia.y, fjz, fay * nib.z);
        st[6] = fmaf(nia.z, fjx, faz * nib.x);
        st[7] = fmaf(nia.z, fjy, faz * nib.y);
        st[8] = fmaf(nia.z, fjz, faz * nib.z);
        __syncwarp();                              // STS visible before TMA issue

        if (active && lane == 0) {
            asm volatile("fence.proxy.async.shared::cta;" ::: "memory");
            float* gdst = out + ((size_t)a * N_ATOMS + bw0) * 9;   // 16B aligned
            unsigned sa = smem_u32(&stage[warp][ai & 1][0]);
            asm volatile("cp.async.bulk.global.shared::cta.bulk_group [%0], [%1], %2;"
                         :: "l"(gdst), "r"(sa), "r"(bytes) : "memory");
            asm volatile("cp.async.bulk.commit_group;" ::: "memory");
        }
    }

    // keep the warp (and CTA smem) alive until this warp's copies drain
    if (lane == 0)
        asm volatile("cp.async.bulk.wait_group %0;" :: "n"(0) : "memory");
}

extern "C" void kernel_launch(void* const* d_in, const int* in_sizes, int n_in,
                              void* d_out, int out_size)
{
    const float* xs    = (const float*)d_in[0];
    const float* xsph  = (const float*)d_in[1];
    const float* coord = (const float*)d_in[2];
    // d_in[3] = fc_edge_index (full graph, i-major; structure known, unused)
    const float* Wsi1 = (const float*)d_in[4];
    const float* Wsi2 = (const float*)d_in[5];
    const float* Wsj1 = (const float*)d_in[6];
    const float* Wsj2 = (const float*)d_in[7];
    const float* Wpi1 = (const float*)d_in[8];
    const float* Wpi2 = (const float*)d_in[9];
    const float* Wpj1 = (const float*)d_in[10];
    const float* Wpj2 = (const float*)d_in[11];
    const float* Wrbf = (const float*)d_in[12];

    node_kernel<<<NB_NODE + NB_TAB, 384>>>(xs, xsph, coord,
                                           Wsi1, Wsi2, Wsj1, Wsj2,
                                           Wpi1, Wpi2, Wpj1, Wpj2, Wrbf);

    dim3 grid((N_ATOMS + BTILE - 1) / BTILE, N_ATOMS / TA);   // (6, 375)
    edge_kernel<<<grid, TB>>>((float*)d_out);
}

// round 16
// speedup vs baseline: 1.1354x; 1.0048x over previous
#include <cuda_runtime.h>
#include <math.h>

#define N_ATOMS 1500
#define NODE_DIM 128
#define HIDDEN 64
#define SPH_DIM 480
#define OFF0 128
#define MUL1E 64
#define HID1E 32
#define NUM_BASIS 20
#define CUTOFF 5.0f

#define TB 256               /* threads per edge block, 8 warps */
#define BTILE 256            /* b's per block (1 edge/thread-lane) */
#define TA 6                 /* a's per block: 1500 = 6*250 */

#define NPB 5
#define NB_NODE 300          /* 300*5 = 1500 exactly */
#define NB_TAB 2
#define TAB_N 512
#define TAB_RANGE 8.0f       /* fc underflows to 0 beyond d ~ 8 */

// node n: [coord.xyz, ni.xyz, nj.xyz] as 3x float4
__device__ float4 g_node[N_ATOMS * 3];
// entry i: (0.5*fc(x_i), 0.5*fc(x_{i+1})), x_i = i*TAB_RANGE/TAB_N
__device__ float2 g_fc2[TAB_N + 1];

__device__ __forceinline__ float sigmoidf_(float x) {
    return 1.0f / (1.0f + __expf(-x));
}

__device__ __forceinline__ unsigned smem_u32(const void* p) {
    unsigned a;
    asm("{ .reg .u64 t; cvta.to.shared.u64 t, %1; cvt.u32.u64 %0, t; }"
        : "=r"(a) : "l"(p));
    return a;
}

// ---------------------------------------------------------------------------
// Stage 1: per-node MLPs, 5 nodes per block. Extra blocks build the fc table.
// ---------------------------------------------------------------------------
__global__ __launch_bounds__(384, 4) void node_kernel(
    const float* __restrict__ xs_g, const float* __restrict__ xsph,
    const float* __restrict__ coord,
    const float* __restrict__ Wsi1, const float* __restrict__ Wsi2,
    const float* __restrict__ Wsj1, const float* __restrict__ Wsj2,
    const float* __restrict__ Wpi1, const float* __restrict__ Wpi2,
    const float* __restrict__ Wpj1, const float* __restrict__ Wpj2,
    const float* __restrict__ Wrbf)
{
    int tid = threadIdx.x;

    if (blockIdx.x >= NB_NODE) {
        // ---- fc table build (pairs) ----
        const float dO = CUTOFF / (float)(NUM_BASIS - 1);
        const float c2e = (-0.5f / (dO * dO)) * 1.4426950408889634f;
        float w[NUM_BASIS];
        #pragma unroll
        for (int k = 0; k < NUM_BASIS; k++) w[k] = __ldg(&Wrbf[k]);
        for (int i = (blockIdx.x - NB_NODE) * 384 + tid; i <= TAB_N; i += NB_TAB * 384) {
            float2 r;
            float x0 = (float)i * (TAB_RANGE / (float)TAB_N);
            float x1 = (float)(i + 1) * (TAB_RANGE / (float)TAB_N);
            float f0 = 0.f, f1 = 0.f;
            #pragma unroll
            for (int k = 0; k < NUM_BASIS; k++) {
                float t0 = x0 - (float)k * dO;
                float t1 = x1 - (float)k * dO;
                f0 = fmaf(w[k], exp2f((c2e * t0) * t0), f0);
                f1 = fmaf(w[k], exp2f((c2e * t1) * t1), f1);
            }
            r.x = 0.5f * f0; r.y = 0.5f * f1;
            g_fc2[i] = r;
        }
        return;
    }

    __shared__ __align__(16) float xs[NPB * NODE_DIM];   // 2.5 KB
    __shared__ float vv[NPB * 192];
    __shared__ float hh[NPB * 192];
    __shared__ float hg[NPB * 192];
    __shared__ float spart[4][NPB];      // per-warp scalar partial sums
    __shared__ float outp[NPB][2][3];

    int n0 = blockIdx.x * NPB;

    for (int i = tid; i < NPB * NODE_DIM; i += 384) xs[i] = xs_g[n0 * NODE_DIM + i];
    for (int i = tid; i < NPB * 192; i += 384) {
        int n = i / 192, k = i - n * 192;
        vv[i] = xsph[(size_t)(n0 + n) * SPH_DIM + OFF0 + k];
    }
    __syncthreads();

    if (tid < 128) {
        int set = tid >> 6, col = tid & 63;
        const float* W1 = set ? Wsj1 : Wsi1;
        const float* W2 = set ? Wsj2 : Wsi2;
        float acc[NPB];
        #pragma unroll
        for (int n = 0; n < NPB; n++) acc[n] = 0.f;
        const float4* xs4 = (const float4*)xs;
        #pragma unroll 4
        for (int k = 0; k < NODE_DIM; k += 4) {
            float w0 = __ldg(&W1[(k + 0) * HIDDEN + col]);
            float w1 = __ldg(&W1[(k + 1) * HIDDEN + col]);
            float w2 = __ldg(&W1[(k + 2) * HIDDEN + col]);
            float w3 = __ldg(&W1[(k + 3) * HIDDEN + col]);
            #pragma unroll
            for (int n = 0; n < NPB; n++) {
                float4 x = xs4[n * (NODE_DIM / 4) + (k >> 2)];
                acc[n] = fmaf(x.x, w0, acc[n]);
                acc[n] = fmaf(x.y, w1, acc[n]);
                acc[n] = fmaf(x.z, w2, acc[n]);
                acc[n] = fmaf(x.w, w3, acc[n]);
            }
        }
        float w2c = __ldg(&W2[col]);
        // warp shuffle reduce over the 32 cols in this warp, for each node
        #pragma unroll
        for (int n = 0; n < NPB; n++) {
            float a = acc[n];
            float v = a * sigmoidf_(a) * w2c;    // silu * W2
            v += __shfl_xor_sync(0xffffffffu, v, 16);
            v += __shfl_xor_sync(0xffffffffu, v, 8);
            v += __shfl_xor_sync(0xffffffffu, v, 4);
            v += __shfl_xor_sync(0xffffffffu, v, 2);
            v += __shfl_xor_sync(0xffffffffu, v, 1);
            if ((tid & 31) == 0) spart[tid >> 5][n] = v;
        }
    } else if (tid < 320) {
        int t = tid - 128;
        int set = t / 96;
        int r = t - set * 96;
        int hc = r / 3, dd = r - hc * 3;
        const float* W1 = set ? Wpj1 : Wpi1;
        float acc[NPB];
        #pragma unroll
        for (int n = 0; n < NPB; n++) acc[n] = 0.f;
        #pragma unroll 4
        for (int m = 0; m < MUL1E; m++) {
            float w = __ldg(&W1[m * HID1E + hc]);
            #pragma unroll
            for (int n = 0; n < NPB; n++)
                acc[n] = fmaf(vv[n * 192 + m * 3 + dd], w, acc[n]);
        }
        #pragma unroll
        for (int n = 0; n < NPB; n++)
            hh[n * 192 + set * 96 + hc * 3 + dd] = acc[n] * 0.125f;   // 1/sqrt(64)
    }
    __syncthreads();

    if (tid >= 128 && tid < 320) {
        int t = tid - 128;
        int set = t / 96;
        int r = t - set * 96;
        int hc = r / 3, dd = r - hc * 3;
        const float* W2 = set ? Wpj2 : Wpi2;
        float w2c = __ldg(&W2[hc]);
        #pragma unroll
        for (int n = 0; n < NPB; n++) {
            int base = n * 192 + set * 96 + hc * 3;
            float h0 = hh[base + 0], h1 = hh[base + 1], h2 = hh[base + 2];
            float nrm = sqrtf(h0 * h0 + h1 * h1 + h2 * h2);
            float gate = sigmoidf_(nrm);
            hg[base + dd] = hh[base + dd] * gate * w2c;
        }
    }
    __syncthreads();

    if (tid < NPB * 6) {                       // (n, set, dd) spherical reduce, 4-way ILP
        int n = tid / 6;
        int r = tid - n * 6;
        int set = r / 3, dd = r - set * 3;
        int base = n * 192 + set * 96 + dd;
        float s0 = 0.f, s1 = 0.f, s2 = 0.f, s3 = 0.f;
        #pragma unroll
        for (int hc = 0; hc < HID1E; hc += 4) {
            s0 += hg[base + (hc + 0) * 3];
            s1 += hg[base + (hc + 1) * 3];
            s2 += hg[base + (hc + 2) * 3];
            s3 += hg[base + (hc + 3) * 3];
        }
        outp[n][set][dd] = ((s0 + s1) + (s2 + s3)) * 0.17677669529663687f;   // 1/sqrt(32)
    }
    __syncthreads();

    if (tid < NPB) {
        int n = n0 + tid;
        float fi = 1.f + spart[0][tid] + spart[1][tid];
        float fj = 1.f + spart[2][tid] + spart[3][tid];
        // e3nn 1e (y,z,x) -> (x,y,z): out[:, [2,0,1]]
        g_node[n * 3 + 0] = make_float4(coord[n * 3 + 0], coord[n * 3 + 1], coord[n * 3 + 2], 0.f);
        g_node[n * 3 + 1] = make_float4(outp[tid][0][2] * fi, outp[tid][0][0] * fi, outp[tid][0][1] * fi, 0.f);
        g_node[n * 3 + 2] = make_float4(outp[tid][1][2] * fj, outp[tid][1][0] * fj, outp[tid][1][1] * fj, 0.f);
    }
}

// ---------------------------------------------------------------------------
// Stage 2: edges, warp-autonomous with per-warp TMA drain.
// Each warp owns 32 consecutive b's and a private double-buffered smem slice
// (2 x 1152 B). Per a: compute 9 comps (stride-9 STS, conflict-free),
// __syncwarp, elected lane issues cp.async.bulk S2G from the slice.
// bulk_group state is per-thread, so warps never couple; no block barriers
// in the mainloop.
// out[a*N+b][r][c] = 0.5 * fc(d_ab) * (ni_a[r]*nj_b[c] + nj_a[r]*ni_b[c])
// ---------------------------------------------------------------------------
__global__ __launch_bounds__(TB, 6) void edge_kernel(float* __restrict__ out)
{
    __shared__ __align__(16) float stage[8][2][288];   // 18 KB
    __shared__ float2 tab2[TAB_N + 1];                 // 4.1 KB

    int tid = threadIdx.x;
    int lane = tid & 31;
    int warp = tid >> 5;

    for (int i = tid; i <= TAB_N; i += TB)
        tab2[i] = __ldg(&g_fc2[i]);
    __syncthreads();                               // table visible to all warps

    int bw0 = blockIdx.x * BTILE + warp * 32;      // this warp's first b
    int nwarp = min(32, N_ATOMS - bw0);            // 32, 28, or <=0 (idle warp)
    bool active = nwarp > 0;

    int bc = min(bw0 + lane, N_ATOMS - 1);         // clamped for safe loads
    const float4* gn = (const float4*)g_node;
    float4 cb  = __ldg(&gn[bc * 3 + 0]);
    float4 nib = __ldg(&gn[bc * 3 + 1]);
    float4 njb = __ldg(&gn[bc * 3 + 2]);

    const float scale = (float)TAB_N / TAB_RANGE;
    const unsigned bytes = (unsigned)(max(nwarp, 0) * 9 * 4);   // 1152/1008, 16B mult
    int a0 = blockIdx.y * TA;
    float* gdst = out + ((size_t)a0 * N_ATOMS + bw0) * 9;       // 16B aligned

    #pragma unroll
    for (int ai = 0; ai < TA; ai++) {
        float4 ca  = __ldg(&gn[(a0 + ai) * 3 + 0]);
        float4 nia = __ldg(&gn[(a0 + ai) * 3 + 1]);
        float4 nja = __ldg(&gn[(a0 + ai) * 3 + 2]);

        float dx = ca.x - cb.x, dy = ca.y - cb.y, dz = ca.z - cb.z;
        float d2 = fmaf(dx, dx, fmaf(dy, dy, dz * dz));
        float d;
        asm("sqrt.approx.f32 %0, %1;" : "=f"(d) : "f"(d2));   // sqrt(0)=0 ok

        float u = fminf(d * scale, (float)TAB_N - 0.001f);
        int i = __float2int_rd(u);
        float frac = u - (float)i;
        float2 t = tab2[i];
        float f = fmaf(frac, t.y - t.x, t.x);      // 0.5*fc(d)

        float fjx = f * njb.x, fjy = f * njb.y, fjz = f * njb.z;
        float fax = f * nja.x, fay = f * nja.y, faz = f * nja.z;

        // buffer reuse: the copy issued from this buffer 2 iters ago must be done
        if (ai >= 2) {
            if (lane == 0)
                asm volatile("cp.async.bulk.wait_group %0;" :: "n"(1) : "memory");
            __syncwarp();
        }

        float* st = &stage[warp][ai & 1][lane * 9];
        st[0] = fmaf(nia.x, fjx, fax * nib.x);
        st[1] = fmaf(nia.x, fjy, fax * nib.y);
        st[2] = fmaf(nia.x, fjz, fax * nib.z);
        st[3] = fmaf(nia.y, fjx, fay * nib.x);
        st[4] = fmaf(nia.y, fjy, fay * nib.y);
        st[5] = fmaf(nia.y, fjz, fay * nib.z);
        st[6] = fmaf(nia.z, fjx, faz * nib.x);
        st[7] = fmaf(nia.z, fjy, faz * nib.y);
        st[8] = fmaf(nia.z, fjz, faz * nib.z);
        __syncwarp();                              // STS visible before TMA issue

        if (active && lane == 0) {
            asm volatile("fence.proxy.async.shared::cta;" ::: "memory");
            unsigned sa = smem_u32(&stage[warp][ai & 1][0]);
            asm volatile("cp.async.bulk.global.shared::cta.bulk_group [%0], [%1], %2;"
                         :: "l"(gdst), "r"(sa), "r"(bytes) : "memory");
            asm volatile("cp.async.bulk.commit_group;" ::: "memory");
        }
        gdst += (size_t)N_ATOMS * 9;
    }

    // keep the warp (and CTA smem) alive until this warp's copies drain
    if (lane == 0)
        asm volatile("cp.async.bulk.wait_group %0;" :: "n"(0) : "memory");
}

extern "C" void kernel_launch(void* const* d_in, const int* in_sizes, int n_in,
                              void* d_out, int out_size)
{
    const float* xs    = (const float*)d_in[0];
    const float* xsph  = (const float*)d_in[1];
    const float* coord = (const float*)d_in[2];
    // d_in[3] = fc_edge_index (full graph, i-major; structure known, unused)
    const float* Wsi1 = (const float*)d_in[4];
    const float* Wsi2 = (const float*)d_in[5];
    const float* Wsj1 = (const float*)d_in[6];
    const float* Wsj2 = (const float*)d_in[7];
    const float* Wpi1 = (const float*)d_in[8];
    const float* Wpi2 = (const float*)d_in[9];
    const float* Wpj1 = (const float*)d_in[10];
    const float* Wpj2 = (const float*)d_in[11];
    const float* Wrbf = (const float*)d_in[12];

    node_kernel<<<NB_NODE + NB_TAB, 384>>>(xs, xsph, coord,
                                           Wsi1, Wsi2, Wsj1, Wsj2,
                                           Wpi1, Wpi2, Wpj1, Wpj2, Wrbf);

    dim3 grid((N_ATOMS + BTILE - 1) / BTILE, N_ATOMS / TA);   // (6, 250)
    edge_kernel<<<grid, TB>>>((float*)d_out);
}